// round 9
// baseline (speedup 1.0000x reference)
#include <cuda_runtime.h>

// PINO elasticity loss on the fixed structured G x G grid mesh.
// R is a constant 7-point 2x2-block stencil (interior); boundary nodes use the
// masked per-triangle path. 8 nodes per thread (4 i x 2 j), float4 center
// loads, all loads preloaded for MLP; single kernel with last-block finalize.

#define G 1024
#define NG (G * G)
#define NBLK 1024  // (G/64) * (G/16)

__device__ double g_acc[2];        // [0] sum of unscaled (Rx^2+Ry^2), [1] sum of unscaled energy
__device__ unsigned int g_count;   // finished-block counter (reset by last block)

__global__ __launch_bounds__(128) void k_main(const float2* __restrict__ up,
                                              const float2* __restrict__ ut,
                                              float* __restrict__ out) {
    const float NU = 0.3f;   // Poisson
    const float SH = 0.35f;  // (1-nu)/2
    const float TN = 0.6f;   // 2*nu

    // Block tile: 64 (j) x 16 (i). Thread: 2 consecutive j, 4 consecutive i.
    int tj = threadIdx.x & 31;
    int ti = threadIdx.x >> 5;           // 0..3
    int j0 = (blockIdx.x << 6) + (tj << 1);   // even -> float4-aligned
    int i0 = (blockIdx.y << 4) + (ti << 2);

    // Clamped column offsets (garbage-but-valid under masks).
    int jw = (j0 > 0) ? -1 : 0;          // west of j0
    int je = (j0 + 2 < G) ? 2 : 1;       // east of j0+1

    const float4* up4 = (const float4*)up;
    const float4* ut4 = (const float4*)ut;

    // Preload 6 up rows (i0-1 .. i0+4): cols j0-1 (W), j0|j0+1 (C0,C1 via f4), j0+2 (E).
    float2 W[6], C0[6], C1[6], E[6];
    #pragma unroll
    for (int r = 0; r < 6; r++) {
        int ri = i0 - 1 + r;
        ri = ri < 0 ? 0 : (ri > G - 1 ? G - 1 : ri);
        int base = (ri << 10) + j0;
        float4 c = up4[base >> 1];
        C0[r] = make_float2(c.x, c.y);
        C1[r] = make_float2(c.z, c.w);
        W[r] = up[base + jw];
        E[r] = up[base + je];
    }
    // Preload 5 ut rows (i0 .. i0+4): cols j0|j0+1 (f4), j0+2.
    float2 TC[5], TD[5], TE[5];
    #pragma unroll
    for (int r = 0; r < 5; r++) {
        int ri = i0 + r;
        ri = ri > G - 1 ? G - 1 : ri;
        int base = (ri << 10) + j0;
        float4 c = ut4[base >> 1];
        TC[r] = make_float2(c.x, c.y);
        TD[r] = make_float2(c.z, c.w);
        TE[r] = ut[base + je];
    }

    float eq = 0.0f, en = 0.0f;

    #pragma unroll
    for (int k = 0; k < 4; k++) {
        int i = i0 + k;
        bool bi0 = (i > 0), bi1 = (i < G - 1);

        #pragma unroll
        for (int jj = 0; jj < 2; jj++) {
            int j = j0 + jj;
            bool bj0 = (j > 0), bj1 = (j < G - 1);

            float2 us = jj ? C1[k]     : C0[k];
            float2 u0 = jj ? C1[k + 1] : C0[k + 1];
            float2 un = jj ? C1[k + 2] : C0[k + 2];
            float2 uw = jj ? C0[k + 1] : W[k + 1];
            float2 ue = jj ? E[k + 1]  : C1[k + 1];
            float2 uP = jj ? C0[k + 2] : W[k + 2];   // (i+1, j-1)
            float2 uQ = jj ? E[k]      : C1[k];      // (i-1, j+1)

            if (bi0 & bi1 & bj0 & bj1) {
                // Assembled interior stencil (unscaled; true R = (0.5/0.91)*this).
                float sxns = un.x + us.x, syns = un.y + us.y;
                float sxew = ue.x + uw.x, syew = ue.y + uw.y;
                float spqx = uP.x + uQ.x, spqy = uP.y + uQ.y;
                float Rx = 5.4f * u0.x + 1.3f * u0.y
                         - 2.0f  * sxns - 0.65f * syns
                         - 0.7f  * sxew - 0.65f * syew
                         + 0.65f * spqy;
                float Ry = 1.3f * u0.x + 5.4f * u0.y
                         - 0.65f * sxns - 0.7f  * syns
                         - 0.65f * sxew - 2.0f  * syew
                         + 0.65f * spqx;
                eq += Rx * Rx + Ry * Ry;
            } else {
                // Boundary: masked sum over the up-to-6 incident triangles.
                float Rx = 0.0f, Ry = 0.0f;
                float e0, e1, e2, s0, s1, s2;
                if (bi1 && bj1) {  // T1: tri1(i,j)   a=u0, b=ue, c=un
                    e0 = un.x - u0.x; e1 = ue.y - u0.y; e2 = (ue.x - u0.x) + (un.y - u0.y);
                    s0 = e0 + NU * e1; s1 = NU * e0 + e1; s2 = SH * e2;
                    Rx -= s0 + s2; Ry -= s1 + s2;
                }
                if (bi1 && bj0) {  // T2: tri1(i,j-1) a=uw, b=u0, c=uP
                    e0 = uP.x - uw.x; e1 = u0.y - uw.y; e2 = (u0.x - uw.x) + (uP.y - uw.y);
                    Rx += SH * e2; Ry += NU * e0 + e1;
                }
                if (bi0 && bj1) {  // T3: tri1(i-1,j) a=us, b=uQ, c=u0
                    e0 = u0.x - us.x; e1 = uQ.y - us.y; e2 = (uQ.x - us.x) + (u0.y - us.y);
                    Rx += e0 + NU * e1; Ry += SH * e2;
                }
                if (bi1 && bj0) {  // T4: tri2(i,j-1) b=u0, d=un, c=uP
                    e0 = un.x - u0.x; e1 = un.y - uP.y; e2 = -u0.y + un.x + un.y - uP.x;
                    Rx -= e0 + NU * e1; Ry -= SH * e2;
                }
                if (bi0 && bj0) {  // T5: tri2(i-1,j-1) b=us, d=u0, c=uw
                    e0 = u0.x - us.x; e1 = u0.y - uw.y; e2 = -us.y + u0.x + u0.y - uw.x;
                    s0 = e0 + NU * e1; s1 = NU * e0 + e1; s2 = SH * e2;
                    Rx += s0 + s2; Ry += s1 + s2;
                }
                if (bi0 && bj1) {  // T6: tri2(i-1,j) b=uQ, d=ue, c=u0
                    e0 = ue.x - uQ.x; e1 = ue.y - u0.y; e2 = -uQ.y + ue.x + ue.y - u0.x;
                    Rx -= SH * e2; Ry -= NU * e0 + e1;
                }
                eq += Rx * Rx + Ry * Ry;
            }

            // Energy for cell (i,j): corners a=(i,j), b=(i,j+1), c=(i+1,j),
            // d=(i+1,j+1) on u_err = u_pred - u_true.
            if (bi1 && bj1) {
                float2 une = jj ? E[k + 2] : C1[k + 2];
                float2 t0 = jj ? TD[k]     : TC[k];
                float2 te = jj ? TE[k]     : TD[k];
                float2 tn = jj ? TD[k + 1] : TC[k + 1];
                float2 tq = jj ? TE[k + 1] : TD[k + 1];
                float ax = u0.x - t0.x,  ay = u0.y - t0.y;
                float bx = ue.x - te.x,  by = ue.y - te.y;
                float cx = un.x - tn.x,  cy = un.y - tn.y;
                float dx = une.x - tq.x, dy = une.y - tq.y;
                float e0 = cx - ax;
                float e1 = by - ay;
                float e2 = (bx - ax) + (cy - ay);
                en += e0 * e0 + e1 * e1 + TN * e0 * e1 + SH * e2 * e2;
                e0 = dx - bx;
                e1 = dy - cy;
                e2 = -by + dx + dy - cx;
                en += e0 * e0 + e1 * e1 + TN * e0 * e1 + SH * e2 * e2;
            }
        }
    }

    // Block reduction (4 warps), then one double-atomic pair per block.
    #pragma unroll
    for (int o = 16; o > 0; o >>= 1) {
        eq += __shfl_xor_sync(0xFFFFFFFFu, eq, o);
        en += __shfl_xor_sync(0xFFFFFFFFu, en, o);
    }
    __shared__ float s_eq[4], s_en[4];
    int w = threadIdx.x >> 5, l = threadIdx.x & 31;
    if (l == 0) { s_eq[w] = eq; s_en[w] = en; }
    __syncthreads();
    if (threadIdx.x == 0) {
        float teq = s_eq[0] + s_eq[1] + s_eq[2] + s_eq[3];
        float ten = s_en[0] + s_en[1] + s_en[2] + s_en[3];
        atomicAdd(&g_acc[0], (double)teq);
        atomicAdd(&g_acc[1], (double)ten);
        __threadfence();
        unsigned int done = atomicAdd(&g_count, 1u);
        if (done == NBLK - 1) {
            // Last block: finalize and reset for the next graph replay.
            const double K = 0.5 / 0.91;               // 0.5 * 1/(1-nu^2)
            double L_eq = (K * K) * g_acc[0] / (2.0 * (double)NG);
            double L_en = K * g_acc[1];                // total_area == 1 exactly
            out[0] = (float)(0.1 * L_eq + 0.1 * L_en);
            g_acc[0] = 0.0;
            g_acc[1] = 0.0;
            g_count = 0u;
        }
    }
}

extern "C" void kernel_launch(void* const* d_in, const int* in_sizes, int n_in,
                              void* d_out, int out_size) {
    const float2* up = (const float2*)d_in[0];
    const float2* ut = (const float2*)d_in[1];
    float* out = (float*)d_out;
    (void)in_sizes; (void)n_in; (void)out_size;

    dim3 grid(G / 64, G / 16);
    k_main<<<grid, 128>>>(up, ut, out);
}